// round 11
// baseline (speedup 1.0000x reference)
#include <cuda_runtime.h>
#include <cuda_bf16.h>

// BitGatConv — algebraic collapse (verified R1-R9, rel_err ~3e-7):
//   vals[i,c] = nhs[i,c] * sum_j softmax(...)[i,j,c] = nhs[i,c]
// => out = nodes_ft @ weight  : [1536,256] @ [256,64]
//
// R10: warp-aligned K-slices. GROUP=32 -> each warp IS one K-slice
// (2 row-pairs x 16 col-quads): weight warp-LDG = one contiguous 256B
// request (2 wavefronts, was 4 with GROUP=48), kh/rem become shifts.
// 384 blocks x 512 thr, occ-3 co-residency, same chip-wide warp count as R9.

#define NROWS        1536
#define KDIM         256
#define K4           (KDIM / 4)         // 64 float4 per row
#define HCDIM        64
#define ROWS_PER_BLK 4
#define RP           (ROWS_PER_BLK / 2) // 2 row-pairs
#define GRID         (NROWS / ROWS_PER_BLK)   // 384 blocks
#define KSPLIT       16
#define GROUP        (RP * 16)                // 32 = one warp per K-slice
#define THREADS      (GROUP * KSPLIT)         // 512
#define K4_PER_TH    (K4 / KSPLIT)            // 4
#define NF_Q         (ROWS_PER_BLK * K4)      // 256 float4 = 4 KB

__global__ __launch_bounds__(THREADS, 3)
void bitgat_nhs_kernel(const float* __restrict__ nodes_ft,
                       const float* __restrict__ weight,
                       float* __restrict__ out)
{
    __shared__ float4 s_nf[NF_Q];                        //  4 KB node tile
    __shared__ float4 s_red[(KSPLIT - 1) * GROUP * 2];   // 15 KB partials

    const int tid  = threadIdx.x;
    const int row0 = blockIdx.x * ROWS_PER_BLK;

    const int kh  = tid >> 5;             // 0..15 K-slice == warp id
    const int rem = tid & 31;
    const int r   = rem >> 4;             // 0..1  row pair (rows r, r+RP)
    const int cq  = rem & 15;             // 0..15 col quad

    const float4* __restrict__ wq  = reinterpret_cast<const float4*>(weight);
    const float4* __restrict__ src = reinterpret_cast<const float4*>(nodes_ft + (size_t)row0 * KDIM);

    // ---- stage node tile: 256 float4 ----
    if (tid < NF_Q)
        s_nf[tid] = src[tid];
    __syncthreads();

    const float4* __restrict__ a0 = &s_nf[ r       * K4 + kh * K4_PER_TH];
    const float4* __restrict__ a1 = &s_nf[(r + RP) * K4 + kh * K4_PER_TH];
    const float4* __restrict__ w  = &wq[(size_t)(kh * K4_PER_TH * 4) * 16 + cq];

    float4 acc0 = make_float4(0.f, 0.f, 0.f, 0.f);
    float4 acc1 = make_float4(0.f, 0.f, 0.f, 0.f);

    #pragma unroll
    for (int k4 = 0; k4 < K4_PER_TH; ++k4) {
        const float4 av0 = a0[k4];                 // LDS.128, 2-way broadcast
        const float4 av1 = a1[k4];
        const float4 w0  = w[(4 * k4 + 0) * 16];   // warp: contiguous 256B
        const float4 w1  = w[(4 * k4 + 1) * 16];
        const float4 w2  = w[(4 * k4 + 2) * 16];
        const float4 w3  = w[(4 * k4 + 3) * 16];

        acc0.x = fmaf(av0.x, w0.x, acc0.x); acc1.x = fmaf(av1.x, w0.x, acc1.x);
        acc0.y = fmaf(av0.x, w0.y, acc0.y); acc1.y = fmaf(av1.x, w0.y, acc1.y);
        acc0.z = fmaf(av0.x, w0.z, acc0.z); acc1.z = fmaf(av1.x, w0.z, acc1.z);
        acc0.w = fmaf(av0.x, w0.w, acc0.w); acc1.w = fmaf(av1.x, w0.w, acc1.w);

        acc0.x = fmaf(av0.y, w1.x, acc0.x); acc1.x = fmaf(av1.y, w1.x, acc1.x);
        acc0.y = fmaf(av0.y, w1.y, acc0.y); acc1.y = fmaf(av1.y, w1.y, acc1.y);
        acc0.z = fmaf(av0.y, w1.z, acc0.z); acc1.z = fmaf(av1.y, w1.z, acc1.z);
        acc0.w = fmaf(av0.y, w1.w, acc0.w); acc1.w = fmaf(av1.y, w1.w, acc1.w);

        acc0.x = fmaf(av0.z, w2.x, acc0.x); acc1.x = fmaf(av1.z, w2.x, acc1.x);
        acc0.y = fmaf(av0.z, w2.y, acc0.y); acc1.y = fmaf(av1.z, w2.y, acc1.y);
        acc0.z = fmaf(av0.z, w2.z, acc0.z); acc1.z = fmaf(av1.z, w2.z, acc1.z);
        acc0.w = fmaf(av0.z, w2.w, acc0.w); acc1.w = fmaf(av1.z, w2.w, acc1.w);

        acc0.x = fmaf(av0.w, w3.x, acc0.x); acc1.x = fmaf(av1.w, w3.x, acc1.x);
        acc0.y = fmaf(av0.w, w3.y, acc0.y); acc1.y = fmaf(av1.w, w3.y, acc1.y);
        acc0.z = fmaf(av0.w, w3.z, acc0.z); acc1.z = fmaf(av1.w, w3.z, acc1.z);
        acc0.w = fmaf(av0.w, w3.w, acc0.w); acc1.w = fmaf(av1.w, w3.w, acc1.w);
    }

    // ---- split-K reduction: kh>0 publish, warp 0 combines + stores ----
    if (kh > 0) {
        float4* p = &s_red[((kh - 1) * GROUP + rem) * 2];
        p[0] = acc0;
        p[1] = acc1;
    }
    __syncthreads();
    if (kh == 0) {
        #pragma unroll
        for (int s = 0; s < KSPLIT - 1; ++s) {
            const float4* p = &s_red[(s * GROUP + rem) * 2];
            const float4 q0 = p[0];
            const float4 q1 = p[1];
            acc0.x += q0.x; acc0.y += q0.y; acc0.z += q0.z; acc0.w += q0.w;
            acc1.x += q1.x; acc1.y += q1.y; acc1.z += q1.z; acc1.w += q1.w;
        }
        float4* dst0 = reinterpret_cast<float4*>(out + (size_t)(row0 + r)      * HCDIM);
        float4* dst1 = reinterpret_cast<float4*>(out + (size_t)(row0 + r + RP) * HCDIM);
        dst0[cq] = acc0;   // STG.128
        dst1[cq] = acc1;
    }
}

extern "C" void kernel_launch(void* const* d_in, const int* in_sizes, int n_in,
                              void* d_out, int out_size)
{
    // metadata order: nodes_ft, adj_bias_mat, weight, conv_weight1, conv_weight2
    const float* nodes_ft = (const float*)d_in[0];
    const float* weight   = (const float*)d_in[2];
    float* out = (float*)d_out;

    (void)in_sizes; (void)n_in; (void)out_size;

    bitgat_nhs_kernel<<<GRID, THREADS>>>(nodes_ft, weight, out);
}

// round 12
// speedup vs baseline: 1.2043x; 1.2043x over previous
#include <cuda_runtime.h>
#include <cuda_bf16.h>

// BitGatConv — algebraic collapse (verified R1-R10, rel_err ~3e-7):
//   vals[i,c] = nhs[i,c] * sum_j softmax(...)[i,j,c] = nhs[i,c]
// => out = nodes_ft @ weight  : [1536,256] @ [256,64]
//
// R11: kill the phase-aligned stage barrier. Node data has zero cross-warp
// reuse -> load it straight from global (16-lane broadcast dedups in L1).
// No smem node tile, no prologue __syncthreads: each warp issues 48
// independent LDGs and runs free. Geometry = R8 best (128 blocks x 768 thr,
// 1 block/SM, warp-aligned GROUP=96).

#define NROWS        1536
#define KDIM         256
#define K4           (KDIM / 4)         // 64 float4 per row
#define HCDIM        64
#define ROWS_PER_BLK 12
#define RP           (ROWS_PER_BLK / 2) // 6 row-pairs
#define GRID         (NROWS / ROWS_PER_BLK)   // 128 blocks = 1/SM
#define KSPLIT       8
#define GROUP        (RP * 16)                // 96 = 3 warps per K-slice
#define THREADS      (GROUP * KSPLIT)         // 768
#define K4_PER_TH    (K4 / KSPLIT)            // 8
#define NF_Q         (ROWS_PER_BLK * K4)

__global__ __launch_bounds__(THREADS)
void bitgat_nhs_kernel(const float* __restrict__ nodes_ft,
                       const float* __restrict__ weight,
                       float* __restrict__ out)
{
    __shared__ float4 s_red[(KSPLIT - 1) * GROUP * 2];   // 21 KB partials

    const int tid  = threadIdx.x;
    const int row0 = blockIdx.x * ROWS_PER_BLK;

    const int kh  = tid / GROUP;          // 0..7  K-slice (3 whole warps each)
    const int rem = tid % GROUP;
    const int r   = rem >> 4;             // 0..5  row pair (rows r, r+RP)
    const int cq  = rem & 15;             // 0..15 col quad

    const float4* __restrict__ wq  = reinterpret_cast<const float4*>(weight);
    const float4* __restrict__ nf4 = reinterpret_cast<const float4*>(nodes_ft);

    // direct global pointers — no staging, no prologue barrier
    const float4* __restrict__ a0 = nf4 + (size_t)(row0 + r)      * K4 + kh * K4_PER_TH;
    const float4* __restrict__ a1 = nf4 + (size_t)(row0 + r + RP) * K4 + kh * K4_PER_TH;
    const float4* __restrict__ w  = wq + (size_t)(kh * K4_PER_TH * 4) * 16 + cq;

    float4 acc0 = make_float4(0.f, 0.f, 0.f, 0.f);
    float4 acc1 = make_float4(0.f, 0.f, 0.f, 0.f);

    #pragma unroll
    for (int k4 = 0; k4 < K4_PER_TH; ++k4) {
        const float4 av0 = a0[k4];                 // LDG.128, 16-lane broadcast
        const float4 av1 = a1[k4];
        const float4 w0  = w[(4 * k4 + 0) * 16];   // LDG.128, contiguous 256B/warp
        const float4 w1  = w[(4 * k4 + 1) * 16];
        const float4 w2  = w[(4 * k4 + 2) * 16];
        const float4 w3  = w[(4 * k4 + 3) * 16];

        acc0.x = fmaf(av0.x, w0.x, acc0.x); acc1.x = fmaf(av1.x, w0.x, acc1.x);
        acc0.y = fmaf(av0.x, w0.y, acc0.y); acc1.y = fmaf(av1.x, w0.y, acc1.y);
        acc0.z = fmaf(av0.x, w0.z, acc0.z); acc1.z = fmaf(av1.x, w0.z, acc1.z);
        acc0.w = fmaf(av0.x, w0.w, acc0.w); acc1.w = fmaf(av1.x, w0.w, acc1.w);

        acc0.x = fmaf(av0.y, w1.x, acc0.x); acc1.x = fmaf(av1.y, w1.x, acc1.x);
        acc0.y = fmaf(av0.y, w1.y, acc0.y); acc1.y = fmaf(av1.y, w1.y, acc1.y);
        acc0.z = fmaf(av0.y, w1.z, acc0.z); acc1.z = fmaf(av1.y, w1.z, acc1.z);
        acc0.w = fmaf(av0.y, w1.w, acc0.w); acc1.w = fmaf(av1.y, w1.w, acc1.w);

        acc0.x = fmaf(av0.z, w2.x, acc0.x); acc1.x = fmaf(av1.z, w2.x, acc1.x);
        acc0.y = fmaf(av0.z, w2.y, acc0.y); acc1.y = fmaf(av1.z, w2.y, acc1.y);
        acc0.z = fmaf(av0.z, w2.z, acc0.z); acc1.z = fmaf(av1.z, w2.z, acc1.z);
        acc0.w = fmaf(av0.z, w2.w, acc0.w); acc1.w = fmaf(av1.z, w2.w, acc1.w);

        acc0.x = fmaf(av0.w, w3.x, acc0.x); acc1.x = fmaf(av1.w, w3.x, acc1.x);
        acc0.y = fmaf(av0.w, w3.y, acc0.y); acc1.y = fmaf(av1.w, w3.y, acc1.y);
        acc0.z = fmaf(av0.w, w3.z, acc0.z); acc1.z = fmaf(av1.w, w3.z, acc1.z);
        acc0.w = fmaf(av0.w, w3.w, acc0.w); acc1.w = fmaf(av1.w, w3.w, acc1.w);
    }

    // ---- split-K reduction: kh>0 publish, kh==0 combines + stores ----
    if (kh > 0) {
        float4* p = &s_red[((kh - 1) * GROUP + rem) * 2];
        p[0] = acc0;
        p[1] = acc1;
    }
    __syncthreads();
    if (kh == 0) {
        #pragma unroll
        for (int s = 0; s < KSPLIT - 1; ++s) {
            const float4* p = &s_red[(s * GROUP + rem) * 2];
            const float4 q0 = p[0];
            const float4 q1 = p[1];
            acc0.x += q0.x; acc0.y += q0.y; acc0.z += q0.z; acc0.w += q0.w;
            acc1.x += q1.x; acc1.y += q1.y; acc1.z += q1.z; acc1.w += q1.w;
        }
        float4* dst0 = reinterpret_cast<float4*>(out + (size_t)(row0 + r)      * HCDIM);
        float4* dst1 = reinterpret_cast<float4*>(out + (size_t)(row0 + r + RP) * HCDIM);
        dst0[cq] = acc0;   // STG.128
        dst1[cq] = acc1;
    }
}

extern "C" void kernel_launch(void* const* d_in, const int* in_sizes, int n_in,
                              void* d_out, int out_size)
{
    // metadata order: nodes_ft, adj_bias_mat, weight, conv_weight1, conv_weight2
    const float* nodes_ft = (const float*)d_in[0];
    const float* weight   = (const float*)d_in[2];
    float* out = (float*)d_out;

    (void)in_sizes; (void)n_in; (void)out_size;

    bitgat_nhs_kernel<<<GRID, THREADS>>>(nodes_ft, weight, out);
}

// round 13
// speedup vs baseline: 1.6000x; 1.3286x over previous
#include <cuda_runtime.h>
#include <cuda_bf16.h>

// BitGatConv — algebraic collapse (verified R1-R11, rel_err ~3e-7):
//   vals[i,c] = nhs[i,c] * sum_j softmax(...)[i,j,c] = nhs[i,c]
// => out = nodes_ft @ weight  : [1536,256] @ [256,64]
//
// R12: R8 skeleton (128 blocks, 1/SM, smem node tile, L1 weight LDG) with
//  - packed fma.rn.f32x2 (halves fma-pipe issue; sm_10x PTX-only form)
//  - 3-row register blocking (weight traffic 384->256 KB/block)
//  - KSPLIT=16, 1024 thr/block, warp-aligned 64-thread K-slices
//  - reduce buffer aliases node tile (45 KB static smem)

#define NROWS        1536
#define KDIM         256
#define K4           (KDIM / 4)          // 64 float4 per row
#define HCDIM        64
#define ROWS_PER_BLK 12
#define RPT          3                    // rows per thread (g, g+4, g+8)
#define NG           (ROWS_PER_BLK / RPT) // 4 row-groups
#define GRID         (NROWS / ROWS_PER_BLK)   // 128 blocks = 1/SM
#define KSPLIT       16
#define GROUP        (NG * 16)                // 64 threads per K-slice
#define THREADS      (GROUP * KSPLIT)         // 1024
#define K4_PER_TH    (K4 / KSPLIT)            // 4
#define NF_Q         (ROWS_PER_BLK * K4)      // 768 float4 = 12 KB
#define RED_SLICES   (KSPLIT - 1)             // 15
#define BUF_Q        (RED_SLICES * RPT * GROUP)  // 2880 float4 = 45 KB

// packed f32x2 helpers
#define SPLAT2(d, f) asm("mov.b64 %0, {%1, %1};" : "=l"(d) : "r"(__float_as_uint(f)))
#define FMA2(d, a, b, c) asm("fma.rn.f32x2 %0, %1, %2, %3;" : "=l"(d) : "l"(a), "l"(b), "l"(c))

union F2U { unsigned long long u; float2 f; };

__global__ __launch_bounds__(THREADS, 1)
void bitgat_nhs_kernel(const float* __restrict__ nodes_ft,
                       const float* __restrict__ weight,
                       float* __restrict__ out)
{
    // buf[0..767] = node tile during compute; whole buf = split-K partials after
    __shared__ float4 s_buf[BUF_Q];   // 45 KB

    const int tid  = threadIdx.x;
    const int row0 = blockIdx.x * ROWS_PER_BLK;

    const int kh  = tid >> 6;             // 0..15 K-slice
    const int rem = tid & 63;
    const int g   = rem >> 4;             // 0..3 row group -> rows g, g+4, g+8
    const int cq  = rem & 15;             // 0..15 col quad

    const float4* __restrict__ src = reinterpret_cast<const float4*>(nodes_ft + (size_t)row0 * KDIM);

    // ---- stage node tile ----
    if (tid < NF_Q)
        s_buf[tid] = src[tid];
    __syncthreads();

    const float4* __restrict__ a0 = &s_buf[(g + 0) * K4 + kh * K4_PER_TH];
    const float4* __restrict__ a1 = &s_buf[(g + 4) * K4 + kh * K4_PER_TH];
    const float4* __restrict__ a2 = &s_buf[(g + 8) * K4 + kh * K4_PER_TH];
    const ulonglong2* __restrict__ w =
        reinterpret_cast<const ulonglong2*>(weight) + (size_t)(kh * K4_PER_TH * 4) * 16 + cq;

    // 3 rows x 4 cols accumulators as packed f32x2 pairs (bit 0 == (0.f,0.f))
    unsigned long long acc[RPT * 2] = {0ull, 0ull, 0ull, 0ull, 0ull, 0ull};

    #pragma unroll
    for (int k4 = 0; k4 < K4_PER_TH; ++k4) {
        const float4 av0 = a0[k4];                       // LDS.128
        const float4 av1 = a1[k4];
        const float4 av2 = a2[k4];
        const ulonglong2 w0 = w[(4 * k4 + 0) * 16];      // LDG.128, 256B/warp
        const ulonglong2 w1 = w[(4 * k4 + 1) * 16];
        const ulonglong2 w2 = w[(4 * k4 + 2) * 16];
        const ulonglong2 w3 = w[(4 * k4 + 3) * 16];

        unsigned long long s;
        #define PROC(F0, F1, F2, W) \
            SPLAT2(s, F0); FMA2(acc[0], s, W.x, acc[0]); FMA2(acc[1], s, W.y, acc[1]); \
            SPLAT2(s, F1); FMA2(acc[2], s, W.x, acc[2]); FMA2(acc[3], s, W.y, acc[3]); \
            SPLAT2(s, F2); FMA2(acc[4], s, W.x, acc[4]); FMA2(acc[5], s, W.y, acc[5]);

        PROC(av0.x, av1.x, av2.x, w0)
        PROC(av0.y, av1.y, av2.y, w1)
        PROC(av0.z, av1.z, av2.z, w2)
        PROC(av0.w, av1.w, av2.w, w3)
        #undef PROC
    }

    // ---- drain node-tile reads, then publish partials into aliased buffer ----
    __syncthreads();
    if (kh > 0) {
        #pragma unroll
        for (int c = 0; c < RPT; ++c) {
            ulonglong2 v; v.x = acc[2 * c]; v.y = acc[2 * c + 1];
            // SoA layout: [(slice + 15*c)*64 + rem] -> contiguous per (c, slice)
            reinterpret_cast<ulonglong2*>(&s_buf[((kh - 1) + RED_SLICES * c) * GROUP + rem])[0] = v;
        }
    }
    __syncthreads();

    // ---- kh==0 combines 15 partial sets and stores ----
    if (kh == 0) {
        #pragma unroll
        for (int c = 0; c < RPT; ++c) {
            F2U lo, hi;
            lo.u = acc[2 * c];
            hi.u = acc[2 * c + 1];
            float4 sum = make_float4(lo.f.x, lo.f.y, hi.f.x, hi.f.y);
            #pragma unroll
            for (int sidx = 0; sidx < RED_SLICES; ++sidx) {
                const float4 p = s_buf[(sidx + RED_SLICES * c) * GROUP + rem];  // conflict-free
                sum.x += p.x; sum.y += p.y; sum.z += p.z; sum.w += p.w;
            }
            float4* dst = reinterpret_cast<float4*>(out + (size_t)(row0 + g + 4 * c) * HCDIM);
            dst[cq] = sum;   // STG.128
        }
    }
}

extern "C" void kernel_launch(void* const* d_in, const int* in_sizes, int n_in,
                              void* d_out, int out_size)
{
    // metadata order: nodes_ft, adj_bias_mat, weight, conv_weight1, conv_weight2
    const float* nodes_ft = (const float*)d_in[0];
    const float* weight   = (const float*)d_in[2];
    float* out = (float*)d_out;

    (void)in_sizes; (void)n_in; (void)out_size;

    bitgat_nhs_kernel<<<GRID, THREADS>>>(nodes_ft, weight, out);
}

// round 15
// speedup vs baseline: 1.6077x; 1.0048x over previous
#include <cuda_runtime.h>
#include <cuda_bf16.h>

// BitGatConv — algebraic collapse (verified R1-R12, rel_err ~3e-7):
//   vals[i,c] = nhs[i,c] * sum_j softmax(...)[i,j,c] = nhs[i,c]
// => out = nodes_ft @ weight  : [1536,256] @ [256,64]
//
// R13: R12 skeleton (128 blocks x 1024 thr, smem node tile, L1 weight LDG,
// f32x2 FMA, RPT=3, KSPLIT=16) plus:
//  - first-iteration weight LDGs prefetched ABOVE the stage barrier
//  - uniform publish-all (48 KB exactly) + 192-thread parallel reduce with
//    packed f32x2 adds (replaces the 2-warp 45-deep serial tail)

#define NROWS        1536
#define KDIM         256
#define K4           (KDIM / 4)          // 64 float4 per row
#define HCDIM        64
#define ROWS_PER_BLK 12
#define RPT          3                    // rows per thread (g, g+4, g+8)
#define NG           (ROWS_PER_BLK / RPT) // 4 row-groups
#define GRID         (NROWS / ROWS_PER_BLK)   // 128 blocks = 1/SM
#define KSPLIT       16
#define GROUP        (NG * 16)                // 64 threads per K-slice
#define THREADS      (GROUP * KSPLIT)         // 1024
#define K4_PER_TH    (K4 / KSPLIT)            // 4
#define NF_Q         (ROWS_PER_BLK * K4)      // 768 float4 = 12 KB
#define BUF_Q        (KSPLIT * RPT * GROUP)   // 3072 float4 = 48 KB exactly

// packed f32x2 helpers
#define SPLAT2(d, f) asm("mov.b64 %0, {%1, %1};" : "=l"(d) : "r"(__float_as_uint(f)))
#define FMA2(d, a, b, c) asm("fma.rn.f32x2 %0, %1, %2, %3;" : "=l"(d) : "l"(a), "l"(b), "l"(c))
#define ADD2(d, a, b) asm("add.rn.f32x2 %0, %1, %2;" : "=l"(d) : "l"(a), "l"(b))

union F2U { unsigned long long u; float2 f; };

__global__ __launch_bounds__(THREADS, 1)
void bitgat_nhs_kernel(const float* __restrict__ nodes_ft,
                       const float* __restrict__ weight,
                       float* __restrict__ out)
{
    // [0..12KB) doubles as node tile during compute; whole 48 KB = partials after
    __shared__ float4 s_buf[BUF_Q];

    const int tid  = threadIdx.x;
    const int row0 = blockIdx.x * ROWS_PER_BLK;

    const int kh  = tid >> 6;             // 0..15 K-slice
    const int rem = tid & 63;
    const int g   = rem >> 4;             // 0..3 row group -> rows g, g+4, g+8
    const int cq  = rem & 15;             // 0..15 col quad

    const float4* __restrict__ src = reinterpret_cast<const float4*>(nodes_ft + (size_t)row0 * KDIM);
    const ulonglong2* __restrict__ w =
        reinterpret_cast<const ulonglong2*>(weight) + (size_t)(kh * K4_PER_TH * 4) * 16 + cq;

    // ---- prefetch first k4-group weights (independent of smem/barrier) ----
    const ulonglong2 pw0 = w[0 * 16];
    const ulonglong2 pw1 = w[1 * 16];
    const ulonglong2 pw2 = w[2 * 16];
    const ulonglong2 pw3 = w[3 * 16];

    // ---- stage node tile ----
    if (tid < NF_Q)
        s_buf[tid] = src[tid];
    __syncthreads();

    const float4* __restrict__ a0 = &s_buf[(g + 0) * K4 + kh * K4_PER_TH];
    const float4* __restrict__ a1 = &s_buf[(g + 4) * K4 + kh * K4_PER_TH];
    const float4* __restrict__ a2 = &s_buf[(g + 8) * K4 + kh * K4_PER_TH];

    // 3 rows x 4 cols accumulators as packed f32x2 pairs
    unsigned long long acc[RPT * 2] = {0ull, 0ull, 0ull, 0ull, 0ull, 0ull};

    unsigned long long s;
    #define PROC(F0, F1, F2, W) \
        SPLAT2(s, F0); FMA2(acc[0], s, W.x, acc[0]); FMA2(acc[1], s, W.y, acc[1]); \
        SPLAT2(s, F1); FMA2(acc[2], s, W.x, acc[2]); FMA2(acc[3], s, W.y, acc[3]); \
        SPLAT2(s, F2); FMA2(acc[4], s, W.x, acc[4]); FMA2(acc[5], s, W.y, acc[5]);

    // ---- k4 = 0: use prefetched weights ----
    {
        const float4 av0 = a0[0];
        const float4 av1 = a1[0];
        const float4 av2 = a2[0];
        PROC(av0.x, av1.x, av2.x, pw0)
        PROC(av0.y, av1.y, av2.y, pw1)
        PROC(av0.z, av1.z, av2.z, pw2)
        PROC(av0.w, av1.w, av2.w, pw3)
    }

    // ---- k4 = 1..3 ----
    #pragma unroll
    for (int k4 = 1; k4 < K4_PER_TH; ++k4) {
        const float4 av0 = a0[k4];                       // LDS.128
        const float4 av1 = a1[k4];
        const float4 av2 = a2[k4];
        const ulonglong2 w0 = w[(4 * k4 + 0) * 16];      // LDG.128, 256B/warp
        const ulonglong2 w1 = w[(4 * k4 + 1) * 16];
        const ulonglong2 w2 = w[(4 * k4 + 2) * 16];
        const ulonglong2 w3 = w[(4 * k4 + 3) * 16];

        PROC(av0.x, av1.x, av2.x, w0)
        PROC(av0.y, av1.y, av2.y, w1)
        PROC(av0.z, av1.z, av2.z, w2)
        PROC(av0.w, av1.w, av2.w, w3)
    }
    #undef PROC

    // ---- drain node-tile reads, then ALL slices publish (SoA, conflict-free) ----
    __syncthreads();
    #pragma unroll
    for (int c = 0; c < RPT; ++c) {
        ulonglong2 v; v.x = acc[2 * c]; v.y = acc[2 * c + 1];
        *reinterpret_cast<ulonglong2*>(&s_buf[(kh * RPT + c) * GROUP + rem]) = v;
    }
    __syncthreads();

    // ---- parallel reduce: 192 threads, one output float4 each ----
    if (tid < RPT * GROUP) {
        const int c   = tid >> 6;        // 0..2
        const int rr  = tid & 63;
        const int gg  = rr >> 4;         // 0..3
        const int qq  = rr & 15;         // 0..15

        unsigned long long s0 = 0ull, s1 = 0ull;
        #pragma unroll
        for (int sl = 0; sl < KSPLIT; ++sl) {
            const ulonglong2 p =
                *reinterpret_cast<const ulonglong2*>(&s_buf[(sl * RPT + c) * GROUP + rr]);
            ADD2(s0, s0, p.x);
            ADD2(s1, s1, p.y);
        }
        F2U lo, hi; lo.u = s0; hi.u = s1;
        float4* dst = reinterpret_cast<float4*>(out + (size_t)(row0 + gg + 4 * c) * HCDIM);
        dst[qq] = make_float4(lo.f.x, lo.f.y, hi.f.x, hi.f.y);   // STG.128
    }
}

extern "C" void kernel_launch(void* const* d_in, const int* in_sizes, int n_in,
                              void* d_out, int out_size)
{
    // metadata order: nodes_ft, adj_bias_mat, weight, conv_weight1, conv_weight2
    const float* nodes_ft = (const float*)d_in[0];
    const float* weight   = (const float*)d_in[2];
    float* out = (float*)d_out;

    (void)in_sizes; (void)n_in; (void)out_size;

    bitgat_nhs_kernel<<<GRID, THREADS>>>(nodes_ft, weight, out);
}